// round 8
// baseline (speedup 1.0000x reference)
#include <cuda_runtime.h>
#include <math.h>

#define B   16
#define C   256
#define H   128
#define Wd  128
#define HW  16384
#define PO  20
#define NP  400
#define MID 16
#define OC  32
#define OH  64
#define OW  64

// ---------------- scratch ----------------
__device__ float g_xp[(size_t)B*C*NP];        // pooled (b,c,400)
__device__ float g_colsum[B*NP];              // sum over channels of xp
__device__ float g_s[B*NP];                   // centered row-means
__device__ float g_x2[(size_t)B*MID*HW];      // grouped channel means
__device__ float g_feat[B*C];
__device__ float g_attn[B*C];
__device__ int   g_maxid[MID];
__device__ float g_scale[MID];
__device__ float g_xc[(size_t)B*OC*HW];
__device__ float g_sp[(size_t)B*2*HW];
__device__ float g_att[(size_t)B*HW];
__device__ float g_y[(size_t)B*OC*OH*OW];
__device__ float g_bnsum[OC], g_bnsum2[OC];

// ---------------- 0. zero accumulators ----------------
__global__ void k_zero() {
    int i = blockIdx.x * 512 + threadIdx.x;
    if (i < B * NP) g_colsum[i] = 0.f;
    if (i < OC) { g_bnsum[i] = 0.f; g_bnsum2[i] = 0.f; }
}

// ---------------- 1. adaptive pool: block per (b,c), coalesced float4 ----------------
// Column bins OVERLAP: bin j = [floor(j*W/20), ceil((j+1)*W/20)). Each column is
// added to every bin containing it (compile-time predicate).
__global__ void k_pool(const float* __restrict__ x) {
    __shared__ float colbin[128 * 20];
    int bc = blockIdx.x;
    int t = threadIdx.x;
    int r = t >> 1, hf = t & 1;
    const float4* src = (const float4*)(x + (size_t)bc * HW + r * Wd + hf * 64);
    float acc[10];
    #pragma unroll
    for (int j = 0; j < 10; j++) acc[j] = 0.f;
    #pragma unroll
    for (int i = 0; i < 16; i++) {
        float4 v = src[i];
        float vv[4];
        vv[0] = v.x; vv[1] = v.y; vv[2] = v.z; vv[3] = v.w;
        #pragma unroll
        for (int comp = 0; comp < 4; comp++) {
            const int cc = i * 4 + comp;
            #pragma unroll
            for (int j = 0; j < 10; j++) {
                const int lws = (j * 32) / 5;
                const int lwe = ((j + 1) * 32 + 4) / 5;
                if (cc >= lws && cc < lwe) acc[j] += vv[comp];
            }
        }
    }
    #pragma unroll
    for (int j = 0; j < 10; j++) colbin[r * 20 + hf * 10 + j] = acc[j];
    __syncthreads();
    int b = bc >> 8;
    for (int o = t; o < NP; o += 256) {
        int oh = o / PO, bw = o % PO;
        int hs = (oh * H) / PO, he = ((oh + 1) * H + PO - 1) / PO;
        int ws = (bw * Wd) / PO, we = ((bw + 1) * Wd + PO - 1) / PO;
        float a = 0.f;
        for (int rr = hs; rr < he; rr++) a += colbin[rr * 20 + bw];
        float val = a / (float)((he - hs) * (we - ws));
        g_xp[(size_t)bc * NP + o] = val;
        atomicAdd(&g_colsum[b * NP + o], val);
    }
}

// ---------------- 1b. grouped channel mean x2 (streaming; runs on side stream) ----------------
__global__ void k_x2(const float* __restrict__ x) {
    int idx = blockIdx.x * 256 + threadIdx.x;
    int pix4 = idx & 4095;
    int mg = (idx >> 12) & 15;
    int b  = idx >> 16;
    const float4* src = (const float4*)(x + ((size_t)(b * C + mg * 16)) * HW) + pix4;
    float4 a = make_float4(0.f, 0.f, 0.f, 0.f);
    #pragma unroll
    for (int j = 0; j < 16; j++) {
        float4 v = src[(size_t)j * (HW / 4)];
        a.x += v.x; a.y += v.y; a.z += v.z; a.w += v.w;
    }
    a.x *= (1.f/16.f); a.y *= (1.f/16.f); a.z *= (1.f/16.f); a.w *= (1.f/16.f);
    ((float4*)g_x2)[idx] = a;
}

// ---------------- 2a. s-vector from colsum ----------------
__global__ void k_sfin() {
    __shared__ float sh[512];
    int b = blockIdx.x, t = threadIdx.x;
    float rm = (t < NP) ? g_colsum[b * NP + t] * (1.f / C) : 0.f;
    sh[t] = rm;
    __syncthreads();
    for (int s = 256; s > 0; s >>= 1) {
        if (t < s) sh[t] += sh[t + s];
        __syncthreads();
    }
    float g = sh[0] / (float)NP;
    if (t < NP) g_s[b * NP + t] = rm - g;
}

// ---------------- 2b. feat: warp per (b,c) ----------------
__global__ void k_feat() {
    int gw = (blockIdx.x * 256 + threadIdx.x) >> 5;
    int lane = threadIdx.x & 31;
    int b = gw >> 8, c = gw & 255;
    const float* xpv = &g_xp[(size_t)(b * C + c) * NP];
    const float* sv  = &g_s[b * NP];
    float acc = 0.f;
    for (int n = lane; n < NP; n += 32) acc += xpv[n] * sv[n];
    #pragma unroll
    for (int o = 16; o; o >>= 1) acc += __shfl_down_sync(0xffffffffu, acc, o);
    if (!lane) g_feat[b * C + c] = acc * (1.f / 399.f);
}

// ---------------- 3a. attn = sigmoid(feat @ W^T + b) ----------------
__global__ void k_attn(const float* __restrict__ lw, const float* __restrict__ lb) {
    int gw = (blockIdx.x * 256 + threadIdx.x) >> 5;
    int lane = threadIdx.x & 31;
    int b = gw >> 8, co = gw & 255;
    const float* f = &g_feat[b * C];
    const float* w = &lw[(size_t)co * C];
    float acc = 0.f;
    for (int c = lane; c < C; c += 32) acc += f[c] * w[c];
    #pragma unroll
    for (int o = 16; o; o >>= 1) acc += __shfl_down_sync(0xffffffffu, acc, o);
    if (!lane) {
        float z = acc + lb[co];
        g_attn[b * C + co] = 1.f / (1.f + __expf(-z));
    }
}

// ---------------- 3b. score mean, stable top-16 ----------------
__global__ void k_select() {
    __shared__ float sc[C];
    __shared__ int sel[C];
    int c = threadIdx.x;
    float a = 0.f;
    for (int b = 0; b < B; b++) a += g_attn[b * C + c];
    float my = a * (1.f / B);
    sc[c] = my;
    __syncthreads();
    int rank = 0;
    for (int j = 0; j < C; j++) {
        float v = sc[j];
        if (v > my || (v == my && j < c)) rank++;
    }
    sel[c] = (rank < MID) ? 1 : 0;
    __syncthreads();
    if (sel[c]) {
        int pos = 0;
        for (int j = 0; j < c; j++) pos += sel[j];
        g_maxid[pos] = c;
        g_scale[pos] = 1.f + my;
    }
}

// ---------------- 4. build xc + mean/max maps ----------------
__global__ void k_xc(const float* __restrict__ x) {
    __shared__ int   mid[MID];
    __shared__ float msc[MID];
    int tid = threadIdx.x;
    if (tid < MID) { mid[tid] = g_maxid[tid]; msc[tid] = g_scale[tid]; }
    __syncthreads();
    int p = blockIdx.x * 256 + tid;
    int b = p >> 14, pix = p & 16383;
    const float* xb = x + (size_t)b * C * HW + pix;
    const float* x2b = &g_x2[(size_t)b * MID * HW + pix];
    float vals[32];
    #pragma unroll
    for (int k = 0; k < MID; k++) vals[k] = xb[(size_t)mid[k] * HW] * msc[k];
    #pragma unroll
    for (int k = 0; k < MID; k++) vals[16 + k] = x2b[(size_t)k * HW];
    float mn = 0.f, mx = -3.4e38f;
    size_t base = (size_t)b * OC * HW + pix;
    #pragma unroll
    for (int k = 0; k < 32; k++) {
        float v = vals[k];
        mn += v;
        mx = fmaxf(mx, v);
        g_xc[base + (size_t)k * HW] = v;
    }
    g_sp[((size_t)b * 2) * HW + pix]     = mn * (1.f / 32.f);
    g_sp[((size_t)b * 2 + 1) * HW + pix] = mx;
}

// ---------------- 5. LSA 7x7 conv + sigmoid -> map ----------------
__global__ void k_lsa(const float* __restrict__ lw) {
    __shared__ float st[2 * 22 * 22];
    __shared__ float wsh[98];
    int b = blockIdx.z;
    int h0 = blockIdx.y * 16, w0 = blockIdx.x * 16;
    int tx = threadIdx.x, ty = threadIdx.y;
    int tid = ty * 16 + tx;
    if (tid < 98) wsh[tid] = lw[tid];
    for (int i = tid; i < 2 * 22 * 22; i += 256) {
        int ci = i / 484, r = i % 484;
        int hh = h0 + r / 22 - 3, ww = w0 + r % 22 - 3;
        float v = 0.f;
        if (hh >= 0 && hh < H && ww >= 0 && ww < Wd)
            v = g_sp[((size_t)(b * 2 + ci)) * HW + hh * Wd + ww];
        st[i] = v;
    }
    __syncthreads();
    float a = 0.f;
    #pragma unroll
    for (int ci = 0; ci < 2; ci++)
        #pragma unroll
        for (int kh = 0; kh < 7; kh++)
            #pragma unroll
            for (int kw = 0; kw < 7; kw++)
                a += st[ci * 484 + (ty + kh) * 22 + (tx + kw)] * wsh[ci * 49 + kh * 7 + kw];
    g_att[(size_t)b * HW + (h0 + ty) * Wd + (w0 + tx)] = 1.f / (1.f + __expf(-a));
}

// ---------------- 6. conv 3x3 s2 p1 (LSA applied on load) + BN sums ----------------
__global__ void k_conv(const float* __restrict__ cw, const float* __restrict__ cb) {
    __shared__ float ws[288 * 33];
    __shared__ __align__(16) float tile[4 * 17 * 24];
    __shared__ float ssum[OC], ssum2[OC];
    int tid = threadIdx.x;
    int b = blockIdx.z;
    int oh0 = blockIdx.y * 8, ow0 = blockIdx.x * 8;
    for (int i = tid; i < 9216; i += 256) {
        int oc_ = i / 288, r = i % 288;
        ws[r * 33 + oc_] = cw[i];
    }
    if (tid < OC) { ssum[tid] = 0.f; ssum2[tid] = 0.f; }
    int oc = tid & 31, orow = tid >> 5;
    float bias = cb[oc];
    float acc[8];
    #pragma unroll
    for (int j = 0; j < 8; j++) acc[j] = bias;
    int ih0 = 2 * oh0 - 1, iw0 = 2 * ow0 - 1;
    const float* attb = &g_att[(size_t)b * HW];
    for (int ic0 = 0; ic0 < 32; ic0 += 4) {
        __syncthreads();
        for (int i = tid; i < 4 * 289; i += 256) {
            int icl = i / 289, rr = (i % 289) / 17, cc = i % 17;
            int ih = ih0 + rr, iw = iw0 + cc;
            float v = 0.f;
            if (ih >= 0 && ih < H && iw >= 0 && iw < Wd)
                v = g_xc[((size_t)(b * OC + ic0 + icl)) * HW + ih * Wd + iw]
                    * attb[ih * Wd + iw];
            tile[(icl * 17 + rr) * 24 + cc] = v;
        }
        __syncthreads();
        #pragma unroll
        for (int icl = 0; icl < 4; icl++) {
            #pragma unroll
            for (int kh = 0; kh < 3; kh++) {
                const float* row = &tile[(icl * 17 + 2 * orow + kh) * 24];
                float r[17];
                float4 q0 = *(const float4*)(row);
                float4 q1 = *(const float4*)(row + 4);
                float4 q2 = *(const float4*)(row + 8);
                float4 q3 = *(const float4*)(row + 12);
                r[0]=q0.x; r[1]=q0.y; r[2]=q0.z; r[3]=q0.w;
                r[4]=q1.x; r[5]=q1.y; r[6]=q1.z; r[7]=q1.w;
                r[8]=q2.x; r[9]=q2.y; r[10]=q2.z; r[11]=q2.w;
                r[12]=q3.x; r[13]=q3.y; r[14]=q3.z; r[15]=q3.w;
                r[16]=row[16];
                const float* wrow = &ws[((ic0 + icl) * 9 + kh * 3) * 33 + oc];
                #pragma unroll
                for (int kw = 0; kw < 3; kw++) {
                    float wv = wrow[kw * 33];
                    #pragma unroll
                    for (int ow = 0; ow < 8; ow++)
                        acc[ow] += r[2 * ow + kw] * wv;
                }
            }
        }
    }
    float ls = 0.f, ls2 = 0.f;
    size_t ybase = ((size_t)(b * OC + oc) * OH + (oh0 + orow)) * OW + ow0;
    #pragma unroll
    for (int ow = 0; ow < 8; ow++) {
        float v = acc[ow];
        ls += v; ls2 += v * v;
        g_y[ybase + ow] = v;
    }
    atomicAdd(&ssum[oc], ls);
    atomicAdd(&ssum2[oc], ls2);
    __syncthreads();
    if (tid < OC) {
        atomicAdd(&g_bnsum[tid], ssum[tid]);
        atomicAdd(&g_bnsum2[tid], ssum2[tid]);
    }
}

// ---------------- 7. BN finalize + apply + SiLU ----------------
__global__ void k_out(const float* __restrict__ gam, const float* __restrict__ bet,
                      float* __restrict__ out) {
    __shared__ float s_s[OC], s_b[OC];
    int t = threadIdx.x;
    if (t < OC) {
        float cnt = (float)(B * OH * OW);
        float mu  = g_bnsum[t] / cnt;
        float var = g_bnsum2[t] / cnt - mu * mu;
        float sc  = gam[t] * rsqrtf(var + 1e-3f);
        s_s[t] = sc;
        s_b[t] = bet[t] - mu * sc;
    }
    __syncthreads();
    int idx4 = blockIdx.x * 256 + t;
    int ch = ((idx4 * 4) >> 12) & 31;
    float4 v = ((const float4*)g_y)[idx4];
    float sc = s_s[ch], bb = s_b[ch];
    float a0 = v.x * sc + bb, a1 = v.y * sc + bb, a2 = v.z * sc + bb, a3 = v.w * sc + bb;
    float4 r;
    r.x = a0 / (1.f + __expf(-a0));
    r.y = a1 / (1.f + __expf(-a1));
    r.z = a2 / (1.f + __expf(-a2));
    r.w = a3 / (1.f + __expf(-a3));
    ((float4*)out)[idx4] = r;
}

// ---------------- launch (fork x2 onto side stream, join before xc) ----------------
static cudaStream_t g_s2;
static cudaEvent_t  g_evFork, g_evJoin;
static bool         g_init = false;

extern "C" void kernel_launch(void* const* d_in, const int* in_sizes, int n_in,
                              void* d_out, int out_size) {
    const float* x    = (const float*)d_in[0];
    const float* lw   = (const float*)d_in[1];
    const float* lb   = (const float*)d_in[2];
    const float* lsa  = (const float*)d_in[3];
    const float* cw   = (const float*)d_in[4];
    const float* cb   = (const float*)d_in[5];
    const float* gam  = (const float*)d_in[6];
    const float* bet  = (const float*)d_in[7];
    float* out = (float*)d_out;

    if (!g_init) {   // one-time resource setup (first call precedes graph capture)
        cudaStreamCreateWithFlags(&g_s2, cudaStreamNonBlocking);
        cudaEventCreateWithFlags(&g_evFork, cudaEventDisableTiming);
        cudaEventCreateWithFlags(&g_evJoin, cudaEventDisableTiming);
        g_init = true;
    }

    // fork: x2 runs on side stream, overlapping pool + SOCA small-kernel chain
    cudaEventRecord(g_evFork, 0);
    cudaStreamWaitEvent(g_s2, g_evFork, 0);
    k_x2<<<4096, 256, 0, g_s2>>>(x);
    cudaEventRecord(g_evJoin, g_s2);

    k_zero<<<13, 512>>>();
    k_pool<<<B * C, 256>>>(x);
    k_sfin<<<B, 512>>>();
    k_feat<<<(B * C) / 8, 256>>>();
    k_attn<<<(B * C) / 8, 256>>>(lw, lb);
    k_select<<<1, C>>>();

    // join: xc needs g_x2
    cudaStreamWaitEvent(0, g_evJoin, 0);
    k_xc<<<(B * HW) / 256, 256>>>(x);
    k_lsa<<<dim3(Wd / 16, H / 16, B), dim3(16, 16)>>>(lsa);
    k_conv<<<dim3(OW / 8, OH / 8, B), 256>>>(cw, cb);
    k_out<<<(B * OC * OH * OW) / 1024, 256>>>(gam, bet, out);
}

// round 9
// speedup vs baseline: 1.1446x; 1.1446x over previous
#include <cuda_runtime.h>
#include <math.h>

#define B   16
#define C   256
#define H   128
#define Wd  128
#define HW  16384
#define PO  20
#define NP  400
#define MID 16
#define OC  32
#define OH  64
#define OW  64

// ---------------- scratch ----------------
__device__ float g_xp[(size_t)B*C*NP];        // pooled (b,c,400)
__device__ float g_colsum[B*NP];              // sum over channels of xp
__device__ float g_s[B*NP];                   // centered row-means
__device__ float g_x2[(size_t)B*MID*HW];      // grouped channel means
__device__ float g_feat[B*C];
__device__ float g_attn[B*C];
__device__ int   g_maxid[MID];
__device__ float g_scale[MID];
__device__ float g_xc[(size_t)B*OC*HW];
__device__ float g_sp[(size_t)B*2*HW];
__device__ float g_att[(size_t)B*HW];
__device__ float g_y[(size_t)B*OC*OH*OW];
__device__ float g_bnsum[OC], g_bnsum2[OC];

// ---------------- 0. zero accumulators ----------------
__global__ void k_zero() {
    int i = blockIdx.x * 512 + threadIdx.x;
    if (i < B * NP) g_colsum[i] = 0.f;
    if (i < OC) { g_bnsum[i] = 0.f; g_bnsum2[i] = 0.f; }
}

// ---------------- 1. FUSED adaptive pool + grouped channel mean ----------------
// Block = (b, mg): 16 channels, read ONCE. Thread = quarter-row (32 contiguous cols).
// Column bins split cleanly per quarter (6.4*5 == 32): local bin ranges
// [0,7) [6,13) [12,20) [19,26) [25,32) — overlap handled at compile time.
// x2 accumulates in registers across the 16 channel phases; nxt prefetch keeps
// DRAM loads in flight across the two phase barriers.
__global__ void __launch_bounds__(512) k_poolx2(const float* __restrict__ x) {
    __shared__ float colbin[128 * 20];     // 10 KB
    int blk = blockIdx.x;
    int b = blk >> 4, mg = blk & 15;
    int t = threadIdx.x;                   // 0..511
    int r = t >> 2, qt = t & 3;
    const float* xg = x + ((size_t)(b * C + mg * 16)) * HW + r * Wd + qt * 32;

    // finalize-task precompute (o = t for t < 400)
    int oh = t / 20, bw = t % 20;
    int hs = (oh * H) / PO, he = ((oh + 1) * H + PO - 1) / PO;
    int wcs = (bw * Wd) / PO, wce = ((bw + 1) * Wd + PO - 1) / PO;
    float inv_area = (t < 400) ? 1.f / (float)((he - hs) * (wce - wcs)) : 0.f;
    float csum = 0.f;

    float4 x2a[8];
    #pragma unroll
    for (int i = 0; i < 8; i++) x2a[i] = make_float4(0.f, 0.f, 0.f, 0.f);

    float4 cur[8], nxt[8];
    #pragma unroll
    for (int i = 0; i < 8; i++) cur[i] = ((const float4*)xg)[i];

    for (int ch = 0; ch < 16; ch++) {
        // unpack + accumulate
        float vv[32];
        #pragma unroll
        for (int i = 0; i < 8; i++) {
            x2a[i].x += cur[i].x; x2a[i].y += cur[i].y;
            x2a[i].z += cur[i].z; x2a[i].w += cur[i].w;
            vv[4*i+0] = cur[i].x; vv[4*i+1] = cur[i].y;
            vv[4*i+2] = cur[i].z; vv[4*i+3] = cur[i].w;
        }
        float bacc[5];
        #pragma unroll
        for (int j = 0; j < 5; j++) bacc[j] = 0.f;
        #pragma unroll
        for (int lc = 0; lc < 32; lc++) {
            #pragma unroll
            for (int j = 0; j < 5; j++) {
                const int lws = (j * 32) / 5;            // 0,6,12,19,25
                const int lwe = ((j + 1) * 32 + 4) / 5;  // 7,13,20,26,32
                if (lc >= lws && lc < lwe) bacc[j] += vv[lc];
            }
        }
        #pragma unroll
        for (int j = 0; j < 5; j++) colbin[r * 20 + qt * 5 + j] = bacc[j];

        // prefetch next channel (in flight across both barriers)
        if (ch < 15) {
            const float* xn = xg + (size_t)(ch + 1) * HW;
            #pragma unroll
            for (int i = 0; i < 8; i++) nxt[i] = ((const float4*)xn)[i];
        }
        __syncthreads();                   // colbin complete
        if (t < 400) {
            float a = 0.f;
            for (int rr = hs; rr < he; rr++) a += colbin[rr * 20 + bw];
            float val = a * inv_area;
            g_xp[((size_t)(b * C + mg * 16 + ch)) * NP + t] = val;
            csum += val;
        }
        __syncthreads();                   // colbin consumed
        #pragma unroll
        for (int i = 0; i < 8; i++) cur[i] = nxt[i];
    }

    if (t < 400) atomicAdd(&g_colsum[b * NP + t], csum);

    float4* dst = (float4*)(&g_x2[((size_t)(b * MID + mg)) * HW]) + r * (Wd / 4) + qt * 8;
    #pragma unroll
    for (int i = 0; i < 8; i++) {
        float4 v = x2a[i];
        v.x *= (1.f/16.f); v.y *= (1.f/16.f); v.z *= (1.f/16.f); v.w *= (1.f/16.f);
        dst[i] = v;
    }
}

// ---------------- 2a. s-vector from colsum ----------------
__global__ void k_sfin() {
    __shared__ float sh[512];
    int b = blockIdx.x, t = threadIdx.x;
    float rm = (t < NP) ? g_colsum[b * NP + t] * (1.f / C) : 0.f;
    sh[t] = rm;
    __syncthreads();
    for (int s = 256; s > 0; s >>= 1) {
        if (t < s) sh[t] += sh[t + s];
        __syncthreads();
    }
    float g = sh[0] / (float)NP;
    if (t < NP) g_s[b * NP + t] = rm - g;
}

// ---------------- 2b. feat: warp per (b,c) ----------------
__global__ void k_feat() {
    int gw = (blockIdx.x * 256 + threadIdx.x) >> 5;
    int lane = threadIdx.x & 31;
    int b = gw >> 8, c = gw & 255;
    const float* xpv = &g_xp[(size_t)(b * C + c) * NP];
    const float* sv  = &g_s[b * NP];
    float acc = 0.f;
    for (int n = lane; n < NP; n += 32) acc += xpv[n] * sv[n];
    #pragma unroll
    for (int o = 16; o; o >>= 1) acc += __shfl_down_sync(0xffffffffu, acc, o);
    if (!lane) g_feat[b * C + c] = acc * (1.f / 399.f);
}

// ---------------- 3a. attn = sigmoid(feat @ W^T + b) ----------------
__global__ void k_attn(const float* __restrict__ lw, const float* __restrict__ lb) {
    int gw = (blockIdx.x * 256 + threadIdx.x) >> 5;
    int lane = threadIdx.x & 31;
    int b = gw >> 8, co = gw & 255;
    const float* f = &g_feat[b * C];
    const float* w = &lw[(size_t)co * C];
    float acc = 0.f;
    for (int c = lane; c < C; c += 32) acc += f[c] * w[c];
    #pragma unroll
    for (int o = 16; o; o >>= 1) acc += __shfl_down_sync(0xffffffffu, acc, o);
    if (!lane) {
        float z = acc + lb[co];
        g_attn[b * C + co] = 1.f / (1.f + __expf(-z));
    }
}

// ---------------- 3b. score mean, stable top-16 ----------------
__global__ void k_select() {
    __shared__ float sc[C];
    __shared__ int sel[C];
    int c = threadIdx.x;
    float a = 0.f;
    for (int b = 0; b < B; b++) a += g_attn[b * C + c];
    float my = a * (1.f / B);
    sc[c] = my;
    __syncthreads();
    int rank = 0;
    for (int j = 0; j < C; j++) {
        float v = sc[j];
        if (v > my || (v == my && j < c)) rank++;
    }
    sel[c] = (rank < MID) ? 1 : 0;
    __syncthreads();
    if (sel[c]) {
        int pos = 0;
        for (int j = 0; j < c; j++) pos += sel[j];
        g_maxid[pos] = c;
        g_scale[pos] = 1.f + my;
    }
}

// ---------------- 4. build xc + mean/max maps ----------------
__global__ void k_xc(const float* __restrict__ x) {
    __shared__ int   mid[MID];
    __shared__ float msc[MID];
    int tid = threadIdx.x;
    if (tid < MID) { mid[tid] = g_maxid[tid]; msc[tid] = g_scale[tid]; }
    __syncthreads();
    int p = blockIdx.x * 256 + tid;
    int b = p >> 14, pix = p & 16383;
    const float* xb = x + (size_t)b * C * HW + pix;
    const float* x2b = &g_x2[(size_t)b * MID * HW + pix];
    float vals[32];
    #pragma unroll
    for (int k = 0; k < MID; k++) vals[k] = xb[(size_t)mid[k] * HW] * msc[k];
    #pragma unroll
    for (int k = 0; k < MID; k++) vals[16 + k] = x2b[(size_t)k * HW];
    float mn = 0.f, mx = -3.4e38f;
    size_t base = (size_t)b * OC * HW + pix;
    #pragma unroll
    for (int k = 0; k < 32; k++) {
        float v = vals[k];
        mn += v;
        mx = fmaxf(mx, v);
        g_xc[base + (size_t)k * HW] = v;
    }
    g_sp[((size_t)b * 2) * HW + pix]     = mn * (1.f / 32.f);
    g_sp[((size_t)b * 2 + 1) * HW + pix] = mx;
}

// ---------------- 5. LSA 7x7 conv + sigmoid -> map ----------------
__global__ void k_lsa(const float* __restrict__ lw) {
    __shared__ float st[2 * 22 * 22];
    __shared__ float wsh[98];
    int b = blockIdx.z;
    int h0 = blockIdx.y * 16, w0 = blockIdx.x * 16;
    int tx = threadIdx.x, ty = threadIdx.y;
    int tid = ty * 16 + tx;
    if (tid < 98) wsh[tid] = lw[tid];
    for (int i = tid; i < 2 * 22 * 22; i += 256) {
        int ci = i / 484, r = i % 484;
        int hh = h0 + r / 22 - 3, ww = w0 + r % 22 - 3;
        float v = 0.f;
        if (hh >= 0 && hh < H && ww >= 0 && ww < Wd)
            v = g_sp[((size_t)(b * 2 + ci)) * HW + hh * Wd + ww];
        st[i] = v;
    }
    __syncthreads();
    float a = 0.f;
    #pragma unroll
    for (int ci = 0; ci < 2; ci++)
        #pragma unroll
        for (int kh = 0; kh < 7; kh++)
            #pragma unroll
            for (int kw = 0; kw < 7; kw++)
                a += st[ci * 484 + (ty + kh) * 22 + (tx + kw)] * wsh[ci * 49 + kh * 7 + kw];
    g_att[(size_t)b * HW + (h0 + ty) * Wd + (w0 + tx)] = 1.f / (1.f + __expf(-a));
}

// ---------------- 6. conv 3x3 s2 p1 (LSA applied on load) + BN sums ----------------
__global__ void k_conv(const float* __restrict__ cw, const float* __restrict__ cb) {
    __shared__ float ws[288 * 33];
    __shared__ __align__(16) float tile[4 * 17 * 24];
    __shared__ float ssum[OC], ssum2[OC];
    int tid = threadIdx.x;
    int b = blockIdx.z;
    int oh0 = blockIdx.y * 8, ow0 = blockIdx.x * 8;
    for (int i = tid; i < 9216; i += 256) {
        int oc_ = i / 288, r = i % 288;
        ws[r * 33 + oc_] = cw[i];
    }
    if (tid < OC) { ssum[tid] = 0.f; ssum2[tid] = 0.f; }
    int oc = tid & 31, orow = tid >> 5;
    float bias = cb[oc];
    float acc[8];
    #pragma unroll
    for (int j = 0; j < 8; j++) acc[j] = bias;
    int ih0 = 2 * oh0 - 1, iw0 = 2 * ow0 - 1;
    const float* attb = &g_att[(size_t)b * HW];
    for (int ic0 = 0; ic0 < 32; ic0 += 4) {
        __syncthreads();
        for (int i = tid; i < 4 * 289; i += 256) {
            int icl = i / 289, rr = (i % 289) / 17, cc = i % 17;
            int ih = ih0 + rr, iw = iw0 + cc;
            float v = 0.f;
            if (ih >= 0 && ih < H && iw >= 0 && iw < Wd)
                v = g_xc[((size_t)(b * OC + ic0 + icl)) * HW + ih * Wd + iw]
                    * attb[ih * Wd + iw];
            tile[(icl * 17 + rr) * 24 + cc] = v;
        }
        __syncthreads();
        #pragma unroll
        for (int icl = 0; icl < 4; icl++) {
            #pragma unroll
            for (int kh = 0; kh < 3; kh++) {
                const float* row = &tile[(icl * 17 + 2 * orow + kh) * 24];
                float r[17];
                float4 q0 = *(const float4*)(row);
                float4 q1 = *(const float4*)(row + 4);
                float4 q2 = *(const float4*)(row + 8);
                float4 q3 = *(const float4*)(row + 12);
                r[0]=q0.x; r[1]=q0.y; r[2]=q0.z; r[3]=q0.w;
                r[4]=q1.x; r[5]=q1.y; r[6]=q1.z; r[7]=q1.w;
                r[8]=q2.x; r[9]=q2.y; r[10]=q2.z; r[11]=q2.w;
                r[12]=q3.x; r[13]=q3.y; r[14]=q3.z; r[15]=q3.w;
                r[16]=row[16];
                const float* wrow = &ws[((ic0 + icl) * 9 + kh * 3) * 33 + oc];
                #pragma unroll
                for (int kw = 0; kw < 3; kw++) {
                    float wv = wrow[kw * 33];
                    #pragma unroll
                    for (int ow = 0; ow < 8; ow++)
                        acc[ow] += r[2 * ow + kw] * wv;
                }
            }
        }
    }
    float ls = 0.f, ls2 = 0.f;
    size_t ybase = ((size_t)(b * OC + oc) * OH + (oh0 + orow)) * OW + ow0;
    #pragma unroll
    for (int ow = 0; ow < 8; ow++) {
        float v = acc[ow];
        ls += v; ls2 += v * v;
        g_y[ybase + ow] = v;
    }
    atomicAdd(&ssum[oc], ls);
    atomicAdd(&ssum2[oc], ls2);
    __syncthreads();
    if (tid < OC) {
        atomicAdd(&g_bnsum[tid], ssum[tid]);
        atomicAdd(&g_bnsum2[tid], ssum2[tid]);
    }
}

// ---------------- 7. BN finalize + apply + SiLU ----------------
__global__ void k_out(const float* __restrict__ gam, const float* __restrict__ bet,
                      float* __restrict__ out) {
    __shared__ float s_s[OC], s_b[OC];
    int t = threadIdx.x;
    if (t < OC) {
        float cnt = (float)(B * OH * OW);
        float mu  = g_bnsum[t] / cnt;
        float var = g_bnsum2[t] / cnt - mu * mu;
        float sc  = gam[t] * rsqrtf(var + 1e-3f);
        s_s[t] = sc;
        s_b[t] = bet[t] - mu * sc;
    }
    __syncthreads();
    int idx4 = blockIdx.x * 256 + t;
    int ch = ((idx4 * 4) >> 12) & 31;
    float4 v = ((const float4*)g_y)[idx4];
    float sc = s_s[ch], bb = s_b[ch];
    float a0 = v.x * sc + bb, a1 = v.y * sc + bb, a2 = v.z * sc + bb, a3 = v.w * sc + bb;
    float4 r;
    r.x = a0 / (1.f + __expf(-a0));
    r.y = a1 / (1.f + __expf(-a1));
    r.z = a2 / (1.f + __expf(-a2));
    r.w = a3 / (1.f + __expf(-a3));
    ((float4*)out)[idx4] = r;
}

// ---------------- launch ----------------
extern "C" void kernel_launch(void* const* d_in, const int* in_sizes, int n_in,
                              void* d_out, int out_size) {
    const float* x    = (const float*)d_in[0];
    const float* lw   = (const float*)d_in[1];
    const float* lb   = (const float*)d_in[2];
    const float* lsa  = (const float*)d_in[3];
    const float* cw   = (const float*)d_in[4];
    const float* cb   = (const float*)d_in[5];
    const float* gam  = (const float*)d_in[6];
    const float* bet  = (const float*)d_in[7];
    float* out = (float*)d_out;

    k_zero<<<13, 512>>>();
    k_poolx2<<<B * MID, 512>>>(x);
    k_sfin<<<B, 512>>>();
    k_feat<<<(B * C) / 8, 256>>>();
    k_attn<<<(B * C) / 8, 256>>>(lw, lb);
    k_select<<<1, C>>>();
    k_xc<<<(B * HW) / 256, 256>>>(x);
    k_lsa<<<dim3(Wd / 16, H / 16, B), dim3(16, 16)>>>(lsa);
    k_conv<<<dim3(OW / 8, OH / 8, B), 256>>>(cw, cb);
    k_out<<<(B * OC * OH * OW) / 1024, 256>>>(gam, bet, out);
}